// round 17
// baseline (speedup 1.0000x reference)
#include <cuda_runtime.h>
#include <math.h>
#include <stdint.h>

#define BATCH 8
#define DIMC 384
#define HEADS 6
#define HD 64
#define HIN 56
#define LQ 3136        // 56*56
#define LKV 784        // 28*28
#define EPS 1e-5f
#define SCALE 0.05103103630798288f   // 384^-0.5

// ---------------- scratch ----------------
__device__ float g_qc[BATCH * LQ  * DIMC];
__device__ float g_kc[BATCH * LKV * DIMC];
__device__ float g_vc[BATCH * LKV * DIMC];
__device__ float g_qp[BATCH * LQ  * DIMC];
__device__ float g_kp[BATCH * LKV * DIMC];
__device__ float g_vp[BATCH * LKV * DIMC];
__device__ float g_ob[BATCH * LQ  * DIMC];

// ---------------- tf32 helpers ----------------
__device__ __forceinline__ uint32_t f2tf(float f) {
    uint32_t u;
    asm("cvt.rna.tf32.f32 %0, %1;" : "=r"(u) : "f"(f));
    return u;
}

__device__ __forceinline__ void mma_tf32(float c[4], const uint32_t a[4], uint32_t b0, uint32_t b1) {
    asm volatile(
        "mma.sync.aligned.m16n8k8.row.col.f32.tf32.tf32.f32 "
        "{%0,%1,%2,%3}, {%4,%5,%6,%7}, {%8,%9}, {%0,%1,%2,%3};\n"
        : "+f"(c[0]), "+f"(c[1]), "+f"(c[2]), "+f"(c[3])
        : "r"(a[0]), "r"(a[1]), "r"(a[2]), "r"(a[3]), "r"(b0), "r"(b1));
}

// ---------------- depthwise 3x3 conv + BN (q path, stride 1) — R14 ----------------
__global__ void dwconv_bn_kernel(const float* __restrict__ x,
                                 const float* __restrict__ wt,
                                 const float* __restrict__ sc,
                                 const float* __restrict__ bb,
                                 const float* __restrict__ mn,
                                 const float* __restrict__ vr,
                                 float* __restrict__ out,
                                 int stride, int Hout)
{
    int idx = blockIdx.x * blockDim.x + threadIdx.x;
    int total = BATCH * Hout * Hout * DIMC;
    if (idx >= total) return;
    int c = idx % DIMC;
    int t = (idx / DIMC) % (Hout * Hout);
    int b = idx / (DIMC * Hout * Hout);
    int oy = t / Hout, ox = t % Hout;

    float acc = 0.f;
#pragma unroll
    for (int dy = 0; dy < 3; dy++) {
        int iy = oy * stride + dy - 1;
        if (iy < 0 || iy >= HIN) continue;
#pragma unroll
        for (int dx = 0; dx < 3; dx++) {
            int ix = ox * stride + dx - 1;
            if (ix < 0 || ix >= HIN) continue;
            acc += x[((size_t)b * LQ + iy * HIN + ix) * DIMC + c] * wt[c * 9 + dy * 3 + dx];
        }
    }
    float inv = rsqrtf(vr[c] + EPS);
    out[idx] = (acc - mn[c]) * inv * sc[c] + bb[c];
}

// ---------------- fused k+v depthwise conv + BN (stride 2) — R14 ----------------
__global__ void dwconv_bn_kv_kernel(const float* __restrict__ x,
                                    const float* __restrict__ wtk,
                                    const float* __restrict__ sck,
                                    const float* __restrict__ bbk,
                                    const float* __restrict__ mnk,
                                    const float* __restrict__ vrk,
                                    const float* __restrict__ wtv,
                                    const float* __restrict__ scv,
                                    const float* __restrict__ bbv,
                                    const float* __restrict__ mnv,
                                    const float* __restrict__ vrv,
                                    float* __restrict__ outk,
                                    float* __restrict__ outv)
{
    int idx = blockIdx.x * blockDim.x + threadIdx.x;
    int total = BATCH * 28 * 28 * DIMC;
    if (idx >= total) return;
    int c = idx % DIMC;
    int t = (idx / DIMC) % (28 * 28);
    int b = idx / (DIMC * 28 * 28);
    int oy = t / 28, ox = t % 28;

    float acck = 0.f, accv = 0.f;
#pragma unroll
    for (int dy = 0; dy < 3; dy++) {
        int iy = oy * 2 + dy - 1;
        if (iy < 0 || iy >= HIN) continue;
#pragma unroll
        for (int dx = 0; dx < 3; dx++) {
            int ix = ox * 2 + dx - 1;
            if (ix < 0 || ix >= HIN) continue;
            float xv = x[((size_t)b * LQ + iy * HIN + ix) * DIMC + c];
            acck += xv * wtk[c * 9 + dy * 3 + dx];
            accv += xv * wtv[c * 9 + dy * 3 + dx];
        }
    }
    float invk = rsqrtf(vrk[c] + EPS);
    float invv = rsqrtf(vrv[c] + EPS);
    outk[idx] = (acck - mnk[c]) * invk * sck[c] + bbk[c];
    outv[idx] = (accv - mnv[c]) * invv * scv[c] + bbv[c];
}

// ---------------- tf32 GEMM body (R11/R12 proven): Y = X @ W^T (+bias) ----------------
#define RSTR 40
#define GAW (128 * RSTR)
#define GEMM_SMEM_BYTES (4 * GAW * 4)   // A0 A1 B0 B1

__device__ __forceinline__ void gemm_body(const float* __restrict__ X,
                                          const float* __restrict__ W,
                                          const float* __restrict__ bias,
                                          float* __restrict__ Y,
                                          int M, int N, int K,
                                          uint32_t* sm)
{
    const int bm = blockIdx.y * 128;
    const int bn = blockIdx.x * 128;
    const int tid = threadIdx.x;
    const int lane = tid & 31;
    const int w = tid >> 5;
    const int g = lane >> 2;
    const int tig = lane & 3;
    const int wm = (w & 1) * 64;
    const int wn = (w >> 1) * 32;

    const int lr = tid >> 1;
    const int lh = tid & 1;

    const float* Xp = X + (size_t)(bm + lr) * K + lh * 8;
    const float* Wp = W + (size_t)(bn + lr) * K + lh * 8;
    const int soff = lr * RSTR + 20 * lh;

    float acc[4][4][4];
#pragma unroll
    for (int i = 0; i < 4; i++)
#pragma unroll
        for (int j = 0; j < 4; j++)
#pragma unroll
            for (int q = 0; q < 4; q++) acc[i][j][q] = 0.f;

    const int nstage = K / 16;
    float4 xa0, xa1, wb0, wb1;

#define G_LOAD(k0) do { \
        xa0 = *(const float4*)(Xp + (k0));     xa1 = *(const float4*)(Xp + (k0) + 4); \
        wb0 = *(const float4*)(Wp + (k0));     wb1 = *(const float4*)(Wp + (k0) + 4); \
    } while (0)

#define G_STORE(buf) do { \
        uint32_t* a  = sm + (buf) * GAW + soff; \
        uint32_t* bq = sm + (2 + (buf)) * GAW + soff; \
        *(uint4*)(a)      = make_uint4(f2tf(xa0.x), f2tf(xa1.x), f2tf(xa0.y), f2tf(xa1.y)); \
        *(uint4*)(a + 4)  = make_uint4(f2tf(xa0.z), f2tf(xa1.z), f2tf(xa0.w), f2tf(xa1.w)); \
        *(uint4*)(bq)     = make_uint4(f2tf(wb0.x), f2tf(wb1.x), f2tf(wb0.y), f2tf(wb1.y)); \
        *(uint4*)(bq + 4) = make_uint4(f2tf(wb0.z), f2tf(wb1.z), f2tf(wb0.w), f2tf(wb1.w)); \
    } while (0)

    G_LOAD(0);
    G_STORE(0);
    __syncthreads();

    for (int s = 0; s < nstage; s++) {
        const int p = s & 1;
        if (s + 1 < nstage) G_LOAD((s + 1) * 16);

        const uint32_t* A = sm + p * GAW;
        const uint32_t* B = sm + (2 + p) * GAW;
#pragma unroll
        for (int gi = 0; gi < 2; gi++) {
            const int goff = 20 * gi;
            uint32_t af[4][4];
#pragma unroll
            for (int mf = 0; mf < 4; mf++) {
                int mb = wm + mf * 16;
                uint2 v1 = *(const uint2*)&A[(mb + g) * RSTR + goff + 2 * tig];
                uint2 v2 = *(const uint2*)&A[(mb + 8 + g) * RSTR + goff + 2 * tig];
                af[mf][0] = v1.x; af[mf][1] = v2.x; af[mf][2] = v1.y; af[mf][3] = v2.y;
            }
            uint2 bf[4];
#pragma unroll
            for (int nf = 0; nf < 4; nf++)
                bf[nf] = *(const uint2*)&B[(wn + nf * 8 + g) * RSTR + goff + 2 * tig];
#pragma unroll
            for (int mf = 0; mf < 4; mf++)
#pragma unroll
                for (int nf = 0; nf < 4; nf++)
                    mma_tf32(acc[mf][nf], af[mf], bf[nf].x, bf[nf].y);
        }

        if (s + 1 < nstage) {
            G_STORE(1 - p);
            __syncthreads();
        }
    }

#pragma unroll
    for (int mf = 0; mf < 4; mf++) {
        int r0 = bm + wm + mf * 16 + g;
#pragma unroll
        for (int nf = 0; nf < 4; nf++) {
            int c0 = bn + wn + nf * 8 + 2 * tig;
            float b0 = bias ? bias[c0] : 0.f;
            float b1 = bias ? bias[c0 + 1] : 0.f;
            *(float2*)&Y[(size_t)r0 * N + c0]       = make_float2(acc[mf][nf][0] + b0, acc[mf][nf][1] + b1);
            *(float2*)&Y[(size_t)(r0 + 8) * N + c0] = make_float2(acc[mf][nf][2] + b0, acc[mf][nf][3] + b1);
        }
    }
}

__global__ __launch_bounds__(256, 2)
void gemm_tf32(const float* __restrict__ X,
               const float* __restrict__ W,
               const float* __restrict__ bias,
               float* __restrict__ Y,
               int M, int N, int K)
{
    extern __shared__ uint32_t sm[];
    gemm_body(X, W, bias, Y, M, N, K, sm);
}

// fused k+v projection: blockIdx.z selects operand set (R15 measured win: 35.5us)
__global__ __launch_bounds__(256, 2)
void gemm_tf32_kv(const float* __restrict__ Xk, const float* __restrict__ Wk, float* __restrict__ Yk,
                  const float* __restrict__ Xv, const float* __restrict__ Wv, float* __restrict__ Yv,
                  int M, int N, int K)
{
    extern __shared__ uint32_t sm[];
    if (blockIdx.z == 0) gemm_body(Xk, Wk, nullptr, Yk, M, N, K, sm);
    else                 gemm_body(Xv, Wv, nullptr, Yv, M, N, K, sm);
}

// ---------------- tf32 flash attention v5: 256 threads, 8 warps x 16 q-rows ----------------
// Identical smem layouts / barrier structure / pipelined K-V loads to R14/R16.
// Only the warp partition changes: 8 warps, one 16-row m-tile each.
#define SQ_STR 68
#define SV_STR 72
#define AQ_W   (128 * SQ_STR)
#define AK_W   (64 * SQ_STR)
#define AV_W   (64 * SV_STR)
#define AP_W   (128 * SQ_STR)
#define ATTN_SMEM_BYTES ((AQ_W + AK_W + AV_W + AP_W) * 4)
#define NKVT 13

__global__ __launch_bounds__(256, 2)
void attn_tf32(const float* __restrict__ Q,
               const float* __restrict__ K,
               const float* __restrict__ V,
               float* __restrict__ O)
{
    extern __shared__ uint32_t smem_u[];
    uint32_t* sQ = smem_u;
    uint32_t* sK = sQ + AQ_W;
    uint32_t* sV = sK + AK_W;
    uint32_t* sP = sV + AV_W;

    const int b = blockIdx.z, h = blockIdx.y;
    const int m0 = blockIdx.x * 128;
    const int tid = threadIdx.x;
    const int lane = tid & 31;
    const int w = tid >> 5;
    const int g = lane >> 2;
    const int tig = lane & 3;
    const int wrow = w * 16;          // warp's q-row base (8 warps x 16 rows)

    const float* Qb = Q + (size_t)b * LQ * DIMC + h * HD;
    for (int i = tid; i < 128 * 16; i += 256) {
        int r = i >> 4, c4 = (i & 15) * 4;
        float4 qv = make_float4(0.f, 0.f, 0.f, 0.f);
        if (m0 + r < LQ)
            qv = *(const float4*)(Qb + (size_t)(m0 + r) * DIMC + c4);
        uint32_t* dst = &sQ[r * SQ_STR + c4];
        dst[0] = f2tf(qv.x); dst[1] = f2tf(qv.y); dst[2] = f2tf(qv.z); dst[3] = f2tf(qv.w);
    }

    float m2[2] = {-1e30f, -1e30f};
    float lsum[2] = {0.f, 0.f};
    float oacc[8][4];
#pragma unroll
    for (int i = 0; i < 8; i++)
#pragma unroll
        for (int j = 0; j < 4; j++) oacc[i][j] = 0.f;

    const float c1 = SCALE * 1.4426950408889634f;
    const float* Kbh = K + (size_t)b * LKV * DIMC + h * HD;
    const float* Vbh = V + (size_t)b * LKV * DIMC + h * HD;

    // register-held next K/V tile: 256 threads, each 4 rows per matrix
    float4 kreg[4], vreg[4];
    const int lrr = tid >> 4;            // base row 0..15
    const int lc4 = (tid & 15) * 4;      // col 0..60

#define KV_LDG(t) do { \
        int _n0 = (t) * 64; \
        _Pragma("unroll") \
        for (int it = 0; it < 4; it++) { \
            int r = lrr + 16 * it; \
            if (_n0 + r < LKV) { \
                kreg[it] = *(const float4*)(Kbh + (size_t)(_n0 + r) * DIMC + lc4); \
                vreg[it] = *(const float4*)(Vbh + (size_t)(_n0 + r) * DIMC + lc4); \
            } else { \
                kreg[it] = make_float4(0.f, 0.f, 0.f, 0.f); \
                vreg[it] = kreg[it]; \
            } \
        } \
    } while (0)

    KV_LDG(0);
    __syncthreads();   // Q staged

    for (int t = 0; t < NKVT; t++) {
        const int n0 = t * 64;
        const int nv = (LKV - n0 < 64) ? (LKV - n0) : 64;

        // ---- STS K/V from registers ----
#pragma unroll
        for (int it = 0; it < 4; it++) {
            int r = lrr + 16 * it;
            uint32_t* dk = &sK[r * SQ_STR + lc4];
            dk[0] = f2tf(kreg[it].x); dk[1] = f2tf(kreg[it].y); dk[2] = f2tf(kreg[it].z); dk[3] = f2tf(kreg[it].w);
            uint32_t* dv = &sV[r * SV_STR + lc4];
            dv[0] = f2tf(vreg[it].x); dv[1] = f2tf(vreg[it].y); dv[2] = f2tf(vreg[it].z); dv[3] = f2tf(vreg[it].w);
        }
        __syncthreads();

        // ---- S = Q @ K^T ----
        float sacc[8][4];
#pragma unroll
        for (int i = 0; i < 8; i++)
#pragma unroll
            for (int j = 0; j < 4; j++) sacc[i][j] = 0.f;

#pragma unroll
        for (int kk = 0; kk < 64; kk += 8) {
            uint32_t aq[4];
            aq[0] = sQ[(wrow + g) * SQ_STR + kk + tig];
            aq[1] = sQ[(wrow + 8 + g) * SQ_STR + kk + tig];
            aq[2] = sQ[(wrow + g) * SQ_STR + kk + tig + 4];
            aq[3] = sQ[(wrow + 8 + g) * SQ_STR + kk + tig + 4];
#pragma unroll
            for (int nf = 0; nf < 8; nf++) {
                uint32_t b0 = sK[(nf * 8 + g) * SQ_STR + kk + tig];
                uint32_t b1 = sK[(nf * 8 + g) * SQ_STR + kk + tig + 4];
                mma_tf32(sacc[nf], aq, b0, b1);
            }
        }

        // ---- online softmax ----
        {
            float mtv[2] = {-1e30f, -1e30f};
#pragma unroll
            for (int nf = 0; nf < 8; nf++) {
#pragma unroll
                for (int c = 0; c < 4; c++) {
                    int col = nf * 8 + 2 * tig + (c & 1);
                    float lg = (col < nv) ? sacc[nf][c] * c1 : -1e30f;
                    sacc[nf][c] = lg;
                    mtv[c >> 1] = fmaxf(mtv[c >> 1], lg);
                }
            }
#pragma unroll
            for (int rr = 0; rr < 2; rr++) {
                mtv[rr] = fmaxf(mtv[rr], __shfl_xor_sync(0xffffffffu, mtv[rr], 1));
                mtv[rr] = fmaxf(mtv[rr], __shfl_xor_sync(0xffffffffu, mtv[rr], 2));
            }
            float corr[2];
#pragma unroll
            for (int rr = 0; rr < 2; rr++) {
                float mn = fmaxf(m2[rr], mtv[rr]);
                corr[rr] = exp2f(m2[rr] - mn);
                m2[rr] = mn;
            }
            float rsum[2] = {0.f, 0.f};
#pragma unroll
            for (int nf = 0; nf < 8; nf++) {
#pragma unroll
                for (int c = 0; c < 4; c++) {
                    int rr = c >> 1;
                    float p = exp2f(sacc[nf][c] - m2[rr]);
                    sacc[nf][c] = p;
                    rsum[rr] += p;
                }
            }
#pragma unroll
            for (int rr = 0; rr < 2; rr++) {
                rsum[rr] += __shfl_xor_sync(0xffffffffu, rsum[rr], 1);
                rsum[rr] += __shfl_xor_sync(0xffffffffu, rsum[rr], 2);
                lsum[rr] = lsum[rr] * corr[rr] + rsum[rr];
            }
#pragma unroll
            for (int nf = 0; nf < 8; nf++) {
                oacc[nf][0] *= corr[0];
                oacc[nf][1] *= corr[0];
                oacc[nf][2] *= corr[1];
                oacc[nf][3] *= corr[1];
            }
            int rb0 = (wrow + g) * SQ_STR;
            int rb1 = (wrow + 8 + g) * SQ_STR;
#pragma unroll
            for (int nf = 0; nf < 8; nf++) {
                int cb = nf * 8 + 2 * tig;
                sP[rb0 + cb]     = f2tf(sacc[nf][0]);
                sP[rb0 + cb + 1] = f2tf(sacc[nf][1]);
                sP[rb1 + cb]     = f2tf(sacc[nf][2]);
                sP[rb1 + cb + 1] = f2tf(sacc[nf][3]);
            }
        }
        __syncwarp();

        // ---- issue next tile's K/V loads (latency covered by PV mma) ----
        if (t + 1 < NKVT) KV_LDG(t + 1);

        // ---- O += P @ V ----
#pragma unroll
        for (int kk = 0; kk < 64; kk += 8) {
            uint32_t ap[4];
            ap[0] = sP[(wrow + g) * SQ_STR + kk + tig];
            ap[1] = sP[(wrow + 8 + g) * SQ_STR + kk + tig];
            ap[2] = sP[(wrow + g) * SQ_STR + kk + tig + 4];
            ap[3] = sP[(wrow + 8 + g) * SQ_STR + kk + tig + 4];
#pragma unroll
            for (int nf = 0; nf < 8; nf++) {
                uint32_t b0 = sV[(kk + tig) * SV_STR + nf * 8 + g];
                uint32_t b1 = sV[(kk + tig + 4) * SV_STR + nf * 8 + g];
                mma_tf32(oacc[nf], ap, b0, b1);
            }
        }
        __syncthreads();
    }

    // epilogue
    float* Ob = O + (size_t)b * LQ * DIMC + h * HD;
    {
        float inv0 = 1.f / lsum[0];
        float inv1 = 1.f / lsum[1];
        int r0 = m0 + wrow + g;
        int r1 = r0 + 8;
#pragma unroll
        for (int nf = 0; nf < 8; nf++) {
            int cb = nf * 8 + 2 * tig;
            if (r0 < LQ)
                *(float2*)&Ob[(size_t)r0 * DIMC + cb] =
                    make_float2(oacc[nf][0] * inv0, oacc[nf][1] * inv0);
            if (r1 < LQ)
                *(float2*)&Ob[(size_t)r1 * DIMC + cb] =
                    make_float2(oacc[nf][2] * inv1, oacc[nf][3] * inv1);
        }
    }
}

// ---------------- launch ----------------
extern "C" void kernel_launch(void* const* d_in, const int* in_sizes, int n_in,
                              void* d_out, int out_size)
{
    const float* x      = (const float*)d_in[0];
    const float* conv_q = (const float*)d_in[3];
    const float* bnq_s  = (const float*)d_in[4];
    const float* bnq_b  = (const float*)d_in[5];
    const float* bnq_m  = (const float*)d_in[6];
    const float* bnq_v  = (const float*)d_in[7];
    const float* conv_k = (const float*)d_in[8];
    const float* bnk_s  = (const float*)d_in[9];
    const float* bnk_b  = (const float*)d_in[10];
    const float* bnk_m  = (const float*)d_in[11];
    const float* bnk_v  = (const float*)d_in[12];
    const float* conv_v = (const float*)d_in[13];
    const float* bnv_s  = (const float*)d_in[14];
    const float* bnv_b  = (const float*)d_in[15];
    const float* bnv_m  = (const float*)d_in[16];
    const float* bnv_v  = (const float*)d_in[17];
    const float* wq     = (const float*)d_in[18];
    const float* wk     = (const float*)d_in[19];
    const float* wv     = (const float*)d_in[20];
    const float* w_last = (const float*)d_in[21];
    const float* b_last = (const float*)d_in[22];

    float *qc, *kc, *vc, *qp, *kp, *vp, *ob;
    cudaGetSymbolAddress((void**)&qc, g_qc);
    cudaGetSymbolAddress((void**)&kc, g_kc);
    cudaGetSymbolAddress((void**)&vc, g_vc);
    cudaGetSymbolAddress((void**)&qp, g_qp);
    cudaGetSymbolAddress((void**)&kp, g_kp);
    cudaGetSymbolAddress((void**)&vp, g_vp);
    cudaGetSymbolAddress((void**)&ob, g_ob);

    cudaFuncSetAttribute(gemm_tf32, cudaFuncAttributeMaxDynamicSharedMemorySize, GEMM_SMEM_BYTES);
    cudaFuncSetAttribute(gemm_tf32_kv, cudaFuncAttributeMaxDynamicSharedMemorySize, GEMM_SMEM_BYTES);
    cudaFuncSetAttribute(attn_tf32, cudaFuncAttributeMaxDynamicSharedMemorySize, ATTN_SMEM_BYTES);

    // depthwise conv + BN: q (stride 1) + fused k/v (stride 2)
    {
        int totq = BATCH * LQ * DIMC;
        int totk = BATCH * LKV * DIMC;
        dwconv_bn_kernel<<<(totq + 255) / 256, 256>>>(x, conv_q, bnq_s, bnq_b, bnq_m, bnq_v, qc, 1, 56);
        dwconv_bn_kv_kernel<<<(totk + 255) / 256, 256>>>(x,
            conv_k, bnk_s, bnk_b, bnk_m, bnk_v,
            conv_v, bnv_s, bnv_b, bnv_m, bnv_v, kc, vc);
    }

    // projections: q alone; k+v fused into one launch (grid z)
    gemm_tf32<<<dim3(DIMC / 128, (BATCH * LQ) / 128), 256, GEMM_SMEM_BYTES>>>(qc, wq, nullptr, qp, BATCH * LQ, DIMC, DIMC);
    gemm_tf32_kv<<<dim3(DIMC / 128, (BATCH * LKV) / 128, 2), 256, GEMM_SMEM_BYTES>>>(
        kc, wk, kp, vc, wv, vp, BATCH * LKV, DIMC, DIMC);

    // attention: 128 q-rows per CTA, 256 threads / 8 warps
    attn_tf32<<<dim3((LQ + 127) / 128, HEADS, BATCH), 256, ATTN_SMEM_BYTES>>>(qp, kp, vp, ob);

    // final projection + bias -> d_out
    gemm_tf32<<<dim3(DIMC / 128, (BATCH * LQ) / 128), 256, GEMM_SMEM_BYTES>>>(ob, w_last, b_last, (float*)d_out,
                                                                              BATCH * LQ, DIMC, DIMC);
}